// round 4
// baseline (speedup 1.0000x reference)
#include <cuda_runtime.h>
#include <math.h>

#define Bv   4
#define Tn   2048
#define Cn   384
#define Hn   6
#define HSn  64
#define BTn  8192
#define BHn  24
#define C4n  1536

// ------------------------- scratch (static device globals) -------------------------
__device__ float g_h[BTn * Cn];
__device__ float g_q[BHn * Tn * HSn];
__device__ float g_k[BHn * Tn * HSn];
__device__ float g_v[BHn * Tn * HSn];
__device__ float g_m[BHn * Tn];          // per-key row max
__device__ float g_iz[BHn * Tn];         // per-key 1/Z
__device__ float g_attn[BTn * Cn];
__device__ float g_x1[BTn * Cn];
__device__ float g_f1[BTn * C4n];

#define SCALE 0.05103103630798287f       // 384^-0.5

// ------------------------- tf32 mma helpers -------------------------
__device__ __forceinline__ float tf32r(float x) {
    unsigned u;
    asm("cvt.rna.tf32.f32 %0, %1;" : "=r"(u) : "f"(x));
    return __uint_as_float(u);
}

__device__ __forceinline__ void mma8(float* c, const unsigned* a, const unsigned* b) {
    asm volatile(
        "mma.sync.aligned.m16n8k8.row.col.f32.tf32.tf32.f32 "
        "{%0,%1,%2,%3}, {%4,%5,%6,%7}, {%8,%9}, {%0,%1,%2,%3};\n"
        : "+f"(c[0]), "+f"(c[1]), "+f"(c[2]), "+f"(c[3])
        : "r"(a[0]), "r"(a[1]), "r"(a[2]), "r"(a[3]), "r"(b[0]), "r"(b[1]));
}

// ------------------------- LayerNorm -------------------------
__global__ void ln_kernel(const float* __restrict__ in, const float* __restrict__ gamma,
                          const float* __restrict__ beta, float* __restrict__ out) {
    int row = blockIdx.x;
    int tid = threadIdx.x;
    const float* p = in + row * Cn;
    float v0 = p[tid], v1 = p[tid + 128], v2 = p[tid + 256];
    float s = v0 + v1 + v2;
    __shared__ float red[4];
    #pragma unroll
    for (int o = 16; o > 0; o >>= 1) s += __shfl_xor_sync(0xffffffffu, s, o);
    if ((tid & 31) == 0) red[tid >> 5] = s;
    __syncthreads();
    float mean = (red[0] + red[1] + red[2] + red[3]) * (1.0f / Cn);
    __syncthreads();
    float d0 = v0 - mean, d1 = v1 - mean, d2 = v2 - mean;
    float q = d0 * d0 + d1 * d1 + d2 * d2;
    #pragma unroll
    for (int o = 16; o > 0; o >>= 1) q += __shfl_xor_sync(0xffffffffu, q, o);
    if ((tid & 31) == 0) red[tid >> 5] = q;
    __syncthreads();
    float var = (red[0] + red[1] + red[2] + red[3]) * (1.0f / Cn);
    float r = rsqrtf(var + 1e-5f);
    float* o = out + row * Cn;
    o[tid]       = d0 * r * gamma[tid]       + beta[tid];
    o[tid + 128] = d1 * r * gamma[tid + 128] + beta[tid + 128];
    o[tid + 256] = d2 * r * gamma[tid + 256] + beta[tid + 256];
}

// ------------------------- generic GEMM (tf32 mma) -------------------------
template <int EPI>
__global__ __launch_bounds__(256)
void gemm_mma(const float* __restrict__ A, const float* __restrict__ Bw,
              const float* __restrict__ bias, const float* __restrict__ resid,
              float* __restrict__ Co, int N, int K) {
    __shared__ float As[128][36];
    __shared__ float Bs[32][68];
    int m0 = blockIdx.y * 128, n0 = blockIdx.x * 64;
    int tid = threadIdx.x, l = tid & 31, w = tid >> 5;
    int wm = (w & 3) * 32, wn = (w >> 2) * 32;
    int g = l >> 2, tg = l & 3;
    float acc[2][4][4] = {};
    for (int k0 = 0; k0 < K; k0 += 32) {
        #pragma unroll
        for (int i = 0; i < 4; i++) {
            int idx = tid + i * 256;
            int m = idx >> 3, kv = (idx & 7) * 4;
            float4 v = *(const float4*)&A[(size_t)(m0 + m) * K + k0 + kv];
            As[m][kv + 0] = tf32r(v.x); As[m][kv + 1] = tf32r(v.y);
            As[m][kv + 2] = tf32r(v.z); As[m][kv + 3] = tf32r(v.w);
        }
        #pragma unroll
        for (int i = 0; i < 2; i++) {
            int idx = tid + i * 256;
            int k = idx >> 4, nv = (idx & 15) * 4;
            float4 v = *(const float4*)&Bw[(size_t)(k0 + k) * N + n0 + nv];
            Bs[k][nv + 0] = tf32r(v.x); Bs[k][nv + 1] = tf32r(v.y);
            Bs[k][nv + 2] = tf32r(v.z); Bs[k][nv + 3] = tf32r(v.w);
        }
        __syncthreads();
        #pragma unroll
        for (int kk = 0; kk < 32; kk += 8) {
            unsigned a[2][4], b[4][2];
            #pragma unroll
            for (int im = 0; im < 2; im++) {
                int r = wm + im * 16;
                a[im][0] = __float_as_uint(As[r + g][kk + tg]);
                a[im][1] = __float_as_uint(As[r + 8 + g][kk + tg]);
                a[im][2] = __float_as_uint(As[r + g][kk + 4 + tg]);
                a[im][3] = __float_as_uint(As[r + 8 + g][kk + 4 + tg]);
            }
            #pragma unroll
            for (int jn = 0; jn < 4; jn++) {
                int c = wn + jn * 8;
                b[jn][0] = __float_as_uint(Bs[kk + tg][c + g]);
                b[jn][1] = __float_as_uint(Bs[kk + 4 + tg][c + g]);
            }
            #pragma unroll
            for (int im = 0; im < 2; im++)
                #pragma unroll
                for (int jn = 0; jn < 4; jn++) mma8(acc[im][jn], a[im], b[jn]);
        }
        __syncthreads();
    }
    #pragma unroll
    for (int im = 0; im < 2; im++) {
        int r0 = m0 + wm + im * 16 + g;
        #pragma unroll
        for (int jn = 0; jn < 4; jn++) {
            int c = n0 + wn + jn * 8 + tg * 2;
            float b0v = bias[c], b1v = bias[c + 1];
            float v00 = acc[im][jn][0] + b0v, v01 = acc[im][jn][1] + b1v;
            float v10 = acc[im][jn][2] + b0v, v11 = acc[im][jn][3] + b1v;
            if (EPI == 0) {
                v00 = fmaxf(v00, 0.f); v01 = fmaxf(v01, 0.f);
                v10 = fmaxf(v10, 0.f); v11 = fmaxf(v11, 0.f);
            } else {
                v00 += resid[(size_t)r0 * N + c];       v01 += resid[(size_t)r0 * N + c + 1];
                v10 += resid[(size_t)(r0 + 8) * N + c]; v11 += resid[(size_t)(r0 + 8) * N + c + 1];
            }
            Co[(size_t)r0 * N + c] = v00;       Co[(size_t)r0 * N + c + 1] = v01;
            Co[(size_t)(r0 + 8) * N + c] = v10; Co[(size_t)(r0 + 8) * N + c + 1] = v11;
        }
    }
}

// ------------------------- QKV (tf32 mma) -------------------------
__global__ __launch_bounds__(256)
void qkv_mma(const float* __restrict__ wq, const float* __restrict__ wk,
             const float* __restrict__ wv) {
    __shared__ float As[128][36];
    __shared__ float Bs[32][68];
    int hh = blockIdx.y;
    const float* W;
    float* O;
    if (blockIdx.z == 0)      { W = wq; O = g_q; }
    else if (blockIdx.z == 1) { W = wk; O = g_k; }
    else                      { W = wv; O = g_v; }
    W += hh * Cn * HSn;
    int m0 = blockIdx.x * 128;
    int tid = threadIdx.x, l = tid & 31, w = tid >> 5;
    int wm = (w & 3) * 32, wn = (w >> 2) * 32;
    int g = l >> 2, tg = l & 3;
    float acc[2][4][4] = {};
    for (int k0 = 0; k0 < Cn; k0 += 32) {
        #pragma unroll
        for (int i = 0; i < 4; i++) {
            int idx = tid + i * 256;
            int m = idx >> 3, kv = (idx & 7) * 4;
            float4 v = *(const float4*)&g_h[(size_t)(m0 + m) * Cn + k0 + kv];
            As[m][kv + 0] = tf32r(v.x); As[m][kv + 1] = tf32r(v.y);
            As[m][kv + 2] = tf32r(v.z); As[m][kv + 3] = tf32r(v.w);
        }
        {
            int idx = tid;
            #pragma unroll
            for (int i = 0; i < 2; i++) {
                int k = idx >> 4, nv = (idx & 15) * 4;
                float4 v = *(const float4*)&W[(size_t)(k0 + k) * HSn + nv];
                Bs[k][nv + 0] = tf32r(v.x); Bs[k][nv + 1] = tf32r(v.y);
                Bs[k][nv + 2] = tf32r(v.z); Bs[k][nv + 3] = tf32r(v.w);
                idx += 256;
            }
        }
        __syncthreads();
        #pragma unroll
        for (int kk = 0; kk < 32; kk += 8) {
            unsigned a[2][4], b[4][2];
            #pragma unroll
            for (int im = 0; im < 2; im++) {
                int r = wm + im * 16;
                a[im][0] = __float_as_uint(As[r + g][kk + tg]);
                a[im][1] = __float_as_uint(As[r + 8 + g][kk + tg]);
                a[im][2] = __float_as_uint(As[r + g][kk + 4 + tg]);
                a[im][3] = __float_as_uint(As[r + 8 + g][kk + 4 + tg]);
            }
            #pragma unroll
            for (int jn = 0; jn < 4; jn++) {
                int c = wn + jn * 8;
                b[jn][0] = __float_as_uint(Bs[kk + tg][c + g]);
                b[jn][1] = __float_as_uint(Bs[kk + 4 + tg][c + g]);
            }
            #pragma unroll
            for (int im = 0; im < 2; im++)
                #pragma unroll
                for (int jn = 0; jn < 4; jn++) mma8(acc[im][jn], a[im], b[jn]);
        }
        __syncthreads();
    }
    #pragma unroll
    for (int im = 0; im < 2; im++) {
        #pragma unroll
        for (int half = 0; half < 2; half++) {
            int m = m0 + wm + im * 16 + g + half * 8;
            int b = m >> 11, t = m & (Tn - 1);
            float* orow = O + (((size_t)(b * Hn + hh) * Tn + t) * HSn);
            #pragma unroll
            for (int jn = 0; jn < 4; jn++) {
                int c = wn + jn * 8 + tg * 2;
                orow[c]     = acc[im][jn][half * 2];
                orow[c + 1] = acc[im][jn][half * 2 + 1];
            }
        }
    }
}

// ------------------------- Pass 1: per-key (m, 1/Z) stats, no score materialization -------------------------
// grid (16 sTiles, 24 bh). Block owns 128 key rows; loops t-tiles >= sTile.
// S tile 128s x 128t: 8 warps, warp tile 32s x 64t. Online (m,Z) in registers.
__global__ __launch_bounds__(256)
void stats_mma() {
    extern __shared__ float sm1[];
    float (*Ks)[68] = (float(*)[68])sm1;               // [s][d]
    float (*Qs)[68] = (float(*)[68])(sm1 + 128 * 68);  // [t][d]
    __shared__ float sm_m[2][128], sm_z[2][128];
    int sT = blockIdx.x, bh = blockIdx.y;
    const float* Kp = g_k + (size_t)bh * Tn * HSn + (size_t)sT * 128 * HSn;
    const float* Qb = g_q + (size_t)bh * Tn * HSn;
    int tid = threadIdx.x, l = tid & 31, w = tid >> 5;
    int g = l >> 2, tg = l & 3;
    int wm = (w & 3) * 32, wn = (w >> 2) * 64;
    #pragma unroll
    for (int i = 0; i < 8; i++) {
        int idx = tid + i * 256;
        int r = idx >> 4, dv = (idx & 15) * 4;
        float4 a = *(const float4*)&Kp[(size_t)r * HSn + dv];
        Ks[r][dv + 0] = tf32r(a.x); Ks[r][dv + 1] = tf32r(a.y);
        Ks[r][dv + 2] = tf32r(a.z); Ks[r][dv + 3] = tf32r(a.w);
    }
    float m_run[4] = {-3.0e38f, -3.0e38f, -3.0e38f, -3.0e38f};
    float z_run[4] = {};
    for (int tT = sT; tT < Tn / 128; tT++) {
        __syncthreads();
        const float* Qp = Qb + (size_t)tT * 128 * HSn;
        #pragma unroll
        for (int i = 0; i < 8; i++) {
            int idx = tid + i * 256;
            int r = idx >> 4, dv = (idx & 15) * 4;
            float4 b = *(const float4*)&Qp[(size_t)r * HSn + dv];
            Qs[r][dv + 0] = tf32r(b.x); Qs[r][dv + 1] = tf32r(b.y);
            Qs[r][dv + 2] = tf32r(b.z); Qs[r][dv + 3] = tf32r(b.w);
        }
        __syncthreads();
        float acc[2][8][4] = {};
        #pragma unroll
        for (int kk = 0; kk < 64; kk += 8) {
            unsigned a[2][4], b[8][2];
            #pragma unroll
            for (int im = 0; im < 2; im++) {
                int r = wm + im * 16;
                a[im][0] = __float_as_uint(Ks[r + g][kk + tg]);
                a[im][1] = __float_as_uint(Ks[r + 8 + g][kk + tg]);
                a[im][2] = __float_as_uint(Ks[r + g][kk + 4 + tg]);
                a[im][3] = __float_as_uint(Ks[r + 8 + g][kk + 4 + tg]);
            }
            #pragma unroll
            for (int jn = 0; jn < 8; jn++) {
                int c = wn + jn * 8;
                b[jn][0] = __float_as_uint(Qs[c + g][kk + tg]);
                b[jn][1] = __float_as_uint(Qs[c + g][kk + 4 + tg]);
            }
            #pragma unroll
            for (int im = 0; im < 2; im++)
                #pragma unroll
                for (int jn = 0; jn < 8; jn++) mma8(acc[im][jn], a[im], b[jn]);
        }
        bool diag = (tT == sT);
        #pragma unroll
        for (int im = 0; im < 2; im++) {
            #pragma unroll
            for (int half = 0; half < 2; half++) {
                int ridx = im * 2 + half;
                int s_loc = wm + im * 16 + g + half * 8;
                int s_glob = sT * 128 + s_loc;
                float vals[16];
                float lm = -3.0e38f;
                #pragma unroll
                for (int jn = 0; jn < 8; jn++) {
                    #pragma unroll
                    for (int c2 = 0; c2 < 2; c2++) {
                        int t_glob = tT * 128 + wn + jn * 8 + tg * 2 + c2;
                        float v = acc[im][jn][half * 2 + c2] * SCALE;
                        if (diag && t_glob < s_glob) v = -3.0e38f;
                        vals[jn * 2 + c2] = v;
                        lm = fmaxf(lm, v);
                    }
                }
                lm = fmaxf(lm, __shfl_xor_sync(0xffffffffu, lm, 1));
                lm = fmaxf(lm, __shfl_xor_sync(0xffffffffu, lm, 2));
                float nm = fmaxf(m_run[ridx], lm);
                float ls = 0.f;
                #pragma unroll
                for (int i = 0; i < 16; i++) ls += __expf(vals[i] - nm);
                ls += __shfl_xor_sync(0xffffffffu, ls, 1);
                ls += __shfl_xor_sync(0xffffffffu, ls, 2);
                z_run[ridx] = z_run[ridx] * __expf(m_run[ridx] - nm) + ls;
                m_run[ridx] = nm;
            }
        }
    }
    int wn2 = w >> 2;
    if (tg == 0) {
        #pragma unroll
        for (int im = 0; im < 2; im++)
            #pragma unroll
            for (int half = 0; half < 2; half++) {
                int s_loc = wm + im * 16 + g + half * 8;
                sm_m[wn2][s_loc] = m_run[im * 2 + half];
                sm_z[wn2][s_loc] = z_run[im * 2 + half];
            }
    }
    __syncthreads();
    if (tid < 128) {
        float m0 = sm_m[0][tid], m1 = sm_m[1][tid];
        float z0 = sm_z[0][tid], z1 = sm_z[1][tid];
        float mm = fmaxf(m0, m1);
        float zz = z0 * __expf(m0 - mm) + z1 * __expf(m1 - mm);
        g_m[bh * Tn + sT * 128 + tid]  = mm;
        g_iz[bh * Tn + sT * 128 + tid] = 1.0f / zz;
    }
}

// ------------------------- Pass 2: fused score-recompute + softmax-apply + AV -------------------------
// grid (16 tTiles reversed, 24 bh). Block owns out tile 128t x 64d; loops s-tiles of 64.
__global__ __launch_bounds__(256, 2)
void fused_av_mma() {
    extern __shared__ float sm2[];
    float (*Qs)[68]  = (float(*)[68])sm2;                       // [t 128][d]
    float (*Ks)[68]  = (float(*)[68])(sm2 + 128 * 68);          // [s 64][d]
    float (*Vs)[68]  = (float(*)[68])(sm2 + 192 * 68);          // [s 64][d]
    float (*Ws)[132] = (float(*)[132])(sm2 + 256 * 68);         // [s 64][t 128]
    int tT = (Tn / 128 - 1) - blockIdx.x;   // big-work blocks first
    int bh = blockIdx.y;
    int b = bh / Hn, h = bh % Hn;
    int t0 = tT * 128;
    const float* Kb = g_k + (size_t)bh * Tn * HSn;
    const float* Vb = g_v + (size_t)bh * Tn * HSn;
    const float* Qp = g_q + (size_t)bh * Tn * HSn + (size_t)t0 * HSn;
    const float* mrow_p = g_m + bh * Tn;
    const float* iz_p   = g_iz + bh * Tn;
    int tid = threadIdx.x, l = tid & 31, w = tid >> 5;
    int g = l >> 2, tg = l & 3;
    // Q resident
    #pragma unroll
    for (int i = 0; i < 8; i++) {
        int idx = tid + i * 256;
        int r = idx >> 4, dv = (idx & 15) * 4;
        float4 v = *(const float4*)&Qp[(size_t)r * HSn + dv];
        Qs[r][dv + 0] = tf32r(v.x); Qs[r][dv + 1] = tf32r(v.y);
        Qs[r][dv + 2] = tf32r(v.z); Qs[r][dv + 3] = tf32r(v.w);
    }
    // S warp layout: 64s x 128t -> warp tile 32s x 32t (2 x 4)
    int wmS = (w & 1) * 32, wnS = (w >> 1) * 32;
    // out warp layout: 128t x 64d -> warp tile 32t x 32d (4 x 2)
    int wmO = (w & 3) * 32, wnO = (w >> 2) * 32;
    float acco[2][4][4] = {};
    for (int s0 = 0; s0 <= t0 + 64; s0 += 64) {
        __syncthreads();
        #pragma unroll
        for (int i = 0; i < 4; i++) {
            int idx = tid + i * 256;
            int r = idx >> 4, dv = (idx & 15) * 4;
            float4 kv = *(const float4*)&Kb[(size_t)(s0 + r) * HSn + dv];
            float4 vv = *(const float4*)&Vb[(size_t)(s0 + r) * HSn + dv];
            Ks[r][dv + 0] = tf32r(kv.x); Ks[r][dv + 1] = tf32r(kv.y);
            Ks[r][dv + 2] = tf32r(kv.z); Ks[r][dv + 3] = tf32r(kv.w);
            Vs[r][dv + 0] = tf32r(vv.x); Vs[r][dv + 1] = tf32r(vv.y);
            Vs[r][dv + 2] = tf32r(vv.z); Vs[r][dv + 3] = tf32r(vv.w);
        }
        __syncthreads();
        // S = K (A, [m=s][k=d]) @ Q^T (B, [n=t][k=d])
        float accs[2][4][4] = {};
        #pragma unroll
        for (int kk = 0; kk < 64; kk += 8) {
            unsigned a[2][4], bfr[4][2];
            #pragma unroll
            for (int im = 0; im < 2; im++) {
                int r = wmS + im * 16;
                a[im][0] = __float_as_uint(Ks[r + g][kk + tg]);
                a[im][1] = __float_as_uint(Ks[r + 8 + g][kk + tg]);
                a[im][2] = __float_as_uint(Ks[r + g][kk + 4 + tg]);
                a[im][3] = __float_as_uint(Ks[r + 8 + g][kk + 4 + tg]);
            }
            #pragma unroll
            for (int jn = 0; jn < 4; jn++) {
                int c = wnS + jn * 8;
                bfr[jn][0] = __float_as_uint(Qs[c + g][kk + tg]);
                bfr[jn][1] = __float_as_uint(Qs[c + g][kk + 4 + tg]);
            }
            #pragma unroll
            for (int im = 0; im < 2; im++)
                #pragma unroll
                for (int jn = 0; jn < 4; jn++) mma8(accs[im][jn], a[im], bfr[jn]);
        }
        // apply exp(S - m_s) * invZ_s, causal mask, store to Ws
        #pragma unroll
        for (int im = 0; im < 2; im++) {
            #pragma unroll
            for (int half = 0; half < 2; half++) {
                int s_loc = wmS + im * 16 + g + half * 8;
                int s_glob = s0 + s_loc;
                float ms = mrow_p[s_glob];
                float iz = iz_p[s_glob];
                #pragma unroll
                for (int jn = 0; jn < 4; jn++) {
                    #pragma unroll
                    for (int c2 = 0; c2 < 2; c2++) {
                        int t_loc = wnS + jn * 8 + tg * 2 + c2;
                        int t_glob = t0 + t_loc;
                        float v = accs[im][jn][half * 2 + c2] * SCALE;
                        float wgt = (t_glob >= s_glob) ? __expf(v - ms) * iz : 0.f;
                        Ws[s_loc][t_loc] = tf32r(wgt);
                    }
                }
            }
        }
        __syncthreads();
        // out[t][d] += W^T (A from Ws[s][t]) @ V (B, [k=s][n=d])
        #pragma unroll
        for (int kk = 0; kk < 64; kk += 8) {
            unsigned a[2][4], bfr[2][2];
            #pragma unroll
            for (int im = 0; im < 2; im++) {
                int r = wmO + im * 16;
                a[im][0] = __float_as_uint(Ws[kk + tg][r + g]);
                a[im][1] = __float_as_uint(Ws[kk + tg][r + 8 + g]);
                a[im][2] = __float_as_uint(Ws[kk + 4 + tg][r + g]);
                a[im][3] = __float_as_uint(Ws[kk + 4 + tg][r + 8 + g]);
            }
            #pragma unroll
            for (int jn = 0; jn < 2; jn++) {
                // only 4 jn of 32d: wnO covers 32, jn 0..3
                ;
            }
            unsigned bf2[4][2];
            #pragma unroll
            for (int jn = 0; jn < 4; jn++) {
                int c = wnO + jn * 8;
                bf2[jn][0] = __float_as_uint(Vs[kk + tg][c + g]);
                bf2[jn][1] = __float_as_uint(Vs[kk + 4 + tg][c + g]);
            }
            #pragma unroll
            for (int im = 0; im < 2; im++)
                #pragma unroll
                for (int jn = 0; jn < 4; jn++) mma8(acco[im][jn], a[im], bf2[jn]);
        }
    }
    // epilogue: write out tile to g_attn (head-merged)
    #pragma unroll
    for (int im = 0; im < 2; im++) {
        #pragma unroll
        for (int half = 0; half < 2; half++) {
            int t = t0 + wmO + im * 16 + g + half * 8;
            float* orow = g_attn + (size_t)(b * Tn + t) * Cn + h * HSn;
            #pragma unroll
            for (int jn = 0; jn < 4; jn++) {
                int d = wnO + jn * 8 + tg * 2;
                float2 v = make_float2(acco[im][jn][half * 2], acco[im][jn][half * 2 + 1]);
                *(float2*)&orow[d] = v;
            }
        }
    }
}

// ------------------------- launch -------------------------
extern "C" void kernel_launch(void* const* d_in, const int* in_sizes, int n_in,
                              void* d_out, int out_size) {
    const float* x      = (const float*)d_in[0];
    const float* wq     = (const float*)d_in[1];
    const float* wk     = (const float*)d_in[2];
    const float* wv     = (const float*)d_in[3];
    const float* w_proj = (const float*)d_in[4];
    const float* b_proj = (const float*)d_in[5];
    const float* w1     = (const float*)d_in[6];
    const float* b1     = (const float*)d_in[7];
    const float* w2     = (const float*)d_in[8];
    const float* b2     = (const float*)d_in[9];
    const float* g1     = (const float*)d_in[10];
    const float* be1    = (const float*)d_in[11];
    const float* g2     = (const float*)d_in[12];
    const float* be2    = (const float*)d_in[13];
    float* out = (float*)d_out;

    float *p_h, *p_x1, *p_attn, *p_f1;
    cudaGetSymbolAddress((void**)&p_h,    g_h);
    cudaGetSymbolAddress((void**)&p_x1,   g_x1);
    cudaGetSymbolAddress((void**)&p_attn, g_attn);
    cudaGetSymbolAddress((void**)&p_f1,   g_f1);

    int smem1 = 2 * 128 * 68 * (int)sizeof(float);           // 69632
    int smem2 = (256 * 68 + 64 * 132) * (int)sizeof(float);  // 103424
    cudaFuncSetAttribute(stats_mma,    cudaFuncAttributeMaxDynamicSharedMemorySize, smem1);
    cudaFuncSetAttribute(fused_av_mma, cudaFuncAttributeMaxDynamicSharedMemorySize, smem2);

    // 1. LN1
    ln_kernel<<<BTn, 128>>>(x, g1, be1, p_h);
    // 2. QKV projections
    qkv_mma<<<dim3(BTn / 128, Hn, 3), 256>>>(wq, wk, wv);
    // 3. Pass 1: per-key softmax stats (no score buffer)
    stats_mma<<<dim3(Tn / 128, BHn), 256, smem1>>>();
    // 4. Pass 2: fused score-recompute + weight + AV + head merge
    fused_av_mma<<<dim3(Tn / 128, BHn), 256, smem2>>>();
    // 5. Output projection + residual 1
    gemm_mma<1><<<dim3(Cn / 64, BTn / 128), 256>>>(p_attn, w_proj, b_proj, x, p_x1, Cn, Cn);
    // 6. LN2
    ln_kernel<<<BTn, 128>>>(p_x1, g2, be2, p_h);
    // 7. MLP up + relu
    gemm_mma<0><<<dim3(C4n / 64, BTn / 128), 256>>>(p_h, w1, b1, nullptr, p_f1, C4n, Cn);
    // 8. MLP down + residual 2 -> out
    gemm_mma<1><<<dim3(Cn / 64, BTn / 128), 256>>>(p_f1, w2, b2, p_x1, out, Cn, C4n);
}

// round 6
// speedup vs baseline: 1.1711x; 1.1711x over previous
#include <cuda_runtime.h>
#include <math.h>

#define Bv   4
#define Tn   2048
#define Cn   384
#define Hn   6
#define HSn  64
#define BTn  8192
#define BHn  24
#define C4n  1536

// ------------------------- scratch (static device globals) -------------------------
__device__ float g_h[BTn * Cn];
__device__ float g_q[BHn * Tn * HSn];
__device__ float g_k[BHn * Tn * HSn];
__device__ float g_v[BHn * Tn * HSn];
__device__ float g_vp[BHn * Tn * HSn];   // V pre-scaled by 1/Z[s]
__device__ float g_z[BHn * Tn];          // per-key sum of exp(S)
__device__ float g_attn[BTn * Cn];
__device__ float g_x1[BTn * Cn];
__device__ float g_f1[BTn * C4n];

#define SCALE 0.05103103630798287f       // 384^-0.5

// ------------------------- tf32 mma helpers -------------------------
__device__ __forceinline__ float tf32r(float x) {
    unsigned u;
    asm("cvt.rna.tf32.f32 %0, %1;" : "=r"(u) : "f"(x));
    return __uint_as_float(u);
}

__device__ __forceinline__ void mma8(float* c, const unsigned* a, const unsigned* b) {
    asm volatile(
        "mma.sync.aligned.m16n8k8.row.col.f32.tf32.tf32.f32 "
        "{%0,%1,%2,%3}, {%4,%5,%6,%7}, {%8,%9}, {%0,%1,%2,%3};\n"
        : "+f"(c[0]), "+f"(c[1]), "+f"(c[2]), "+f"(c[3])
        : "r"(a[0]), "r"(a[1]), "r"(a[2]), "r"(a[3]), "r"(b[0]), "r"(b[1]));
}

__device__ __forceinline__ void red2(float* p, float x, float y) {
    asm volatile("red.global.add.v2.f32 [%0], {%1,%2};" :: "l"(p), "f"(x), "f"(y) : "memory");
}

// ------------------------- LayerNorm -------------------------
__global__ void ln_kernel(const float* __restrict__ in, const float* __restrict__ gamma,
                          const float* __restrict__ beta, float* __restrict__ out) {
    int row = blockIdx.x;
    int tid = threadIdx.x;
    const float* p = in + row * Cn;
    float v0 = p[tid], v1 = p[tid + 128], v2 = p[tid + 256];
    float s = v0 + v1 + v2;
    __shared__ float red[4];
    #pragma unroll
    for (int o = 16; o > 0; o >>= 1) s += __shfl_xor_sync(0xffffffffu, s, o);
    if ((tid & 31) == 0) red[tid >> 5] = s;
    __syncthreads();
    float mean = (red[0] + red[1] + red[2] + red[3]) * (1.0f / Cn);
    __syncthreads();
    float d0 = v0 - mean, d1 = v1 - mean, d2 = v2 - mean;
    float q = d0 * d0 + d1 * d1 + d2 * d2;
    #pragma unroll
    for (int o = 16; o > 0; o >>= 1) q += __shfl_xor_sync(0xffffffffu, q, o);
    if ((tid & 31) == 0) red[tid >> 5] = q;
    __syncthreads();
    float var = (red[0] + red[1] + red[2] + red[3]) * (1.0f / Cn);
    float r = rsqrtf(var + 1e-5f);
    float* o = out + row * Cn;
    o[tid]       = d0 * r * gamma[tid]       + beta[tid];
    o[tid + 128] = d1 * r * gamma[tid + 128] + beta[tid + 128];
    o[tid + 256] = d2 * r * gamma[tid + 256] + beta[tid + 256];
}

// ------------------------- generic GEMM (tf32 mma) -------------------------
template <int EPI>
__global__ __launch_bounds__(256)
void gemm_mma(const float* __restrict__ A, const float* __restrict__ Bw,
              const float* __restrict__ bias, const float* __restrict__ resid,
              float* __restrict__ Co, int N, int K) {
    __shared__ float As[128][36];
    __shared__ float Bs[32][68];
    int m0 = blockIdx.y * 128, n0 = blockIdx.x * 64;
    int tid = threadIdx.x, l = tid & 31, w = tid >> 5;
    int wm = (w & 3) * 32, wn = (w >> 2) * 32;
    int g = l >> 2, tg = l & 3;
    float acc[2][4][4] = {};
    for (int k0 = 0; k0 < K; k0 += 32) {
        #pragma unroll
        for (int i = 0; i < 4; i++) {
            int idx = tid + i * 256;
            int m = idx >> 3, kv = (idx & 7) * 4;
            float4 v = *(const float4*)&A[(size_t)(m0 + m) * K + k0 + kv];
            As[m][kv + 0] = tf32r(v.x); As[m][kv + 1] = tf32r(v.y);
            As[m][kv + 2] = tf32r(v.z); As[m][kv + 3] = tf32r(v.w);
        }
        #pragma unroll
        for (int i = 0; i < 2; i++) {
            int idx = tid + i * 256;
            int k = idx >> 4, nv = (idx & 15) * 4;
            float4 v = *(const float4*)&Bw[(size_t)(k0 + k) * N + n0 + nv];
            Bs[k][nv + 0] = tf32r(v.x); Bs[k][nv + 1] = tf32r(v.y);
            Bs[k][nv + 2] = tf32r(v.z); Bs[k][nv + 3] = tf32r(v.w);
        }
        __syncthreads();
        #pragma unroll
        for (int kk = 0; kk < 32; kk += 8) {
            unsigned a[2][4], b[4][2];
            #pragma unroll
            for (int im = 0; im < 2; im++) {
                int r = wm + im * 16;
                a[im][0] = __float_as_uint(As[r + g][kk + tg]);
                a[im][1] = __float_as_uint(As[r + 8 + g][kk + tg]);
                a[im][2] = __float_as_uint(As[r + g][kk + 4 + tg]);
                a[im][3] = __float_as_uint(As[r + 8 + g][kk + 4 + tg]);
            }
            #pragma unroll
            for (int jn = 0; jn < 4; jn++) {
                int c = wn + jn * 8;
                b[jn][0] = __float_as_uint(Bs[kk + tg][c + g]);
                b[jn][1] = __float_as_uint(Bs[kk + 4 + tg][c + g]);
            }
            #pragma unroll
            for (int im = 0; im < 2; im++)
                #pragma unroll
                for (int jn = 0; jn < 4; jn++) mma8(acc[im][jn], a[im], b[jn]);
        }
        __syncthreads();
    }
    #pragma unroll
    for (int im = 0; im < 2; im++) {
        int r0 = m0 + wm + im * 16 + g;
        #pragma unroll
        for (int jn = 0; jn < 4; jn++) {
            int c = n0 + wn + jn * 8 + tg * 2;
            float b0v = bias[c], b1v = bias[c + 1];
            float v00 = acc[im][jn][0] + b0v, v01 = acc[im][jn][1] + b1v;
            float v10 = acc[im][jn][2] + b0v, v11 = acc[im][jn][3] + b1v;
            if (EPI == 0) {
                v00 = fmaxf(v00, 0.f); v01 = fmaxf(v01, 0.f);
                v10 = fmaxf(v10, 0.f); v11 = fmaxf(v11, 0.f);
            } else {
                v00 += resid[(size_t)r0 * N + c];       v01 += resid[(size_t)r0 * N + c + 1];
                v10 += resid[(size_t)(r0 + 8) * N + c]; v11 += resid[(size_t)(r0 + 8) * N + c + 1];
            }
            Co[(size_t)r0 * N + c] = v00;       Co[(size_t)r0 * N + c + 1] = v01;
            Co[(size_t)(r0 + 8) * N + c] = v10; Co[(size_t)(r0 + 8) * N + c + 1] = v11;
        }
    }
}

// ------------------------- QKV (tf32 mma) -------------------------
__global__ __launch_bounds__(256)
void qkv_mma(const float* __restrict__ wq, const float* __restrict__ wk,
             const float* __restrict__ wv) {
    __shared__ float As[128][36];
    __shared__ float Bs[32][68];
    int hh = blockIdx.y;
    const float* W;
    float* O;
    if (blockIdx.z == 0)      { W = wq; O = g_q; }
    else if (blockIdx.z == 1) { W = wk; O = g_k; }
    else                      { W = wv; O = g_v; }
    W += hh * Cn * HSn;
    int m0 = blockIdx.x * 128;
    int tid = threadIdx.x, l = tid & 31, w = tid >> 5;
    int wm = (w & 3) * 32, wn = (w >> 2) * 32;
    int g = l >> 2, tg = l & 3;
    float acc[2][4][4] = {};
    for (int k0 = 0; k0 < Cn; k0 += 32) {
        #pragma unroll
        for (int i = 0; i < 4; i++) {
            int idx = tid + i * 256;
            int m = idx >> 3, kv = (idx & 7) * 4;
            float4 v = *(const float4*)&g_h[(size_t)(m0 + m) * Cn + k0 + kv];
            As[m][kv + 0] = tf32r(v.x); As[m][kv + 1] = tf32r(v.y);
            As[m][kv + 2] = tf32r(v.z); As[m][kv + 3] = tf32r(v.w);
        }
        {
            int idx = tid;
            #pragma unroll
            for (int i = 0; i < 2; i++) {
                int k = idx >> 4, nv = (idx & 15) * 4;
                float4 v = *(const float4*)&W[(size_t)(k0 + k) * HSn + nv];
                Bs[k][nv + 0] = tf32r(v.x); Bs[k][nv + 1] = tf32r(v.y);
                Bs[k][nv + 2] = tf32r(v.z); Bs[k][nv + 3] = tf32r(v.w);
                idx += 256;
            }
        }
        __syncthreads();
        #pragma unroll
        for (int kk = 0; kk < 32; kk += 8) {
            unsigned a[2][4], b[4][2];
            #pragma unroll
            for (int im = 0; im < 2; im++) {
                int r = wm + im * 16;
                a[im][0] = __float_as_uint(As[r + g][kk + tg]);
                a[im][1] = __float_as_uint(As[r + 8 + g][kk + tg]);
                a[im][2] = __float_as_uint(As[r + g][kk + 4 + tg]);
                a[im][3] = __float_as_uint(As[r + 8 + g][kk + 4 + tg]);
            }
            #pragma unroll
            for (int jn = 0; jn < 4; jn++) {
                int c = wn + jn * 8;
                b[jn][0] = __float_as_uint(Bs[kk + tg][c + g]);
                b[jn][1] = __float_as_uint(Bs[kk + 4 + tg][c + g]);
            }
            #pragma unroll
            for (int im = 0; im < 2; im++)
                #pragma unroll
                for (int jn = 0; jn < 4; jn++) mma8(acc[im][jn], a[im], b[jn]);
        }
        __syncthreads();
    }
    #pragma unroll
    for (int im = 0; im < 2; im++) {
        #pragma unroll
        for (int half = 0; half < 2; half++) {
            int m = m0 + wm + im * 16 + g + half * 8;
            int b = m >> 11, t = m & (Tn - 1);
            float* orow = O + (((size_t)(b * Hn + hh) * Tn + t) * HSn);
            #pragma unroll
            for (int jn = 0; jn < 4; jn++) {
                int c = wn + jn * 8 + tg * 2;
                orow[c]     = acc[im][jn][half * 2];
                orow[c + 1] = acc[im][jn][half * 2 + 1];
            }
        }
    }
}

// ------------------------- Pass 1: Z[s] = sum_t>=s exp(scale*K[s]·Q[t])  (no max needed) -------------------------
// grid (tT=16, sT=16, bh=24); tiles with tT < sT return immediately. atomicAdd into g_z.
__global__ __launch_bounds__(256)
void zsum_mma() {
    extern __shared__ float sm1[];
    float (*Ks)[68] = (float(*)[68])sm1;               // [s][d]
    float (*Qs)[68] = (float(*)[68])(sm1 + 128 * 68);  // [t][d]
    int tT = blockIdx.x, sT = blockIdx.y, bh = blockIdx.z;
    if (tT < sT) return;
    const float* Kp = g_k + (size_t)bh * Tn * HSn + (size_t)sT * 128 * HSn;
    const float* Qp = g_q + (size_t)bh * Tn * HSn + (size_t)tT * 128 * HSn;
    int tid = threadIdx.x, l = tid & 31, w = tid >> 5;
    int g = l >> 2, tg = l & 3;
    int wm = (w & 3) * 32, wn = (w >> 2) * 64;
    #pragma unroll
    for (int i = 0; i < 8; i++) {
        int idx = tid + i * 256;
        int r = idx >> 4, dv = (idx & 15) * 4;
        float4 a = *(const float4*)&Kp[(size_t)r * HSn + dv];
        float4 b = *(const float4*)&Qp[(size_t)r * HSn + dv];
        Ks[r][dv + 0] = tf32r(a.x); Ks[r][dv + 1] = tf32r(a.y);
        Ks[r][dv + 2] = tf32r(a.z); Ks[r][dv + 3] = tf32r(a.w);
        Qs[r][dv + 0] = tf32r(b.x); Qs[r][dv + 1] = tf32r(b.y);
        Qs[r][dv + 2] = tf32r(b.z); Qs[r][dv + 3] = tf32r(b.w);
    }
    __syncthreads();
    float acc[2][8][4] = {};
    #pragma unroll
    for (int kk = 0; kk < 64; kk += 8) {
        unsigned a[2][4], b[8][2];
        #pragma unroll
        for (int im = 0; im < 2; im++) {
            int r = wm + im * 16;
            a[im][0] = __float_as_uint(Ks[r + g][kk + tg]);
            a[im][1] = __float_as_uint(Ks[r + 8 + g][kk + tg]);
            a[im][2] = __float_as_uint(Ks[r + g][kk + 4 + tg]);
            a[im][3] = __float_as_uint(Ks[r + 8 + g][kk + 4 + tg]);
        }
        #pragma unroll
        for (int jn = 0; jn < 8; jn++) {
            int c = wn + jn * 8;
            b[jn][0] = __float_as_uint(Qs[c + g][kk + tg]);
            b[jn][1] = __float_as_uint(Qs[c + g][kk + 4 + tg]);
        }
        #pragma unroll
        for (int im = 0; im < 2; im++)
            #pragma unroll
            for (int jn = 0; jn < 8; jn++) mma8(acc[im][jn], a[im], b[jn]);
    }
    bool diag = (tT == sT);
    #pragma unroll
    for (int im = 0; im < 2; im++) {
        #pragma unroll
        for (int half = 0; half < 2; half++) {
            int s_loc = wm + im * 16 + g + half * 8;
            int s_glob = sT * 128 + s_loc;
            float ls = 0.f;
            #pragma unroll
            for (int jn = 0; jn < 8; jn++) {
                #pragma unroll
                for (int c2 = 0; c2 < 2; c2++) {
                    int t_glob = tT * 128 + wn + jn * 8 + tg * 2 + c2;
                    float e = __expf(acc[im][jn][half * 2 + c2] * SCALE);
                    if (diag && t_glob < s_glob) e = 0.f;
                    ls += e;
                }
            }
            ls += __shfl_xor_sync(0xffffffffu, ls, 1);
            ls += __shfl_xor_sync(0xffffffffu, ls, 2);
            if (tg == 0) atomicAdd(&g_z[bh * Tn + s_glob], ls);
        }
    }
}

// ------------------------- V' = V / Z[s] -------------------------
__global__ void vscale_kernel() {
    int idx = blockIdx.x * 256 + threadIdx.x;            // float4 index
    int row = idx >> 4;                                  // HSn/4 = 16 float4 per row
    float inv = __fdividef(1.0f, g_z[row]);
    float4 v = ((const float4*)g_v)[idx];
    v.x *= inv; v.y *= inv; v.z *= inv; v.w *= inv;
    ((float4*)g_vp)[idx] = v;
}

// ------------------------- Pass 2: partial AV with recompute, RED accumulate -------------------------
// grid (tT=16, sc=8, bh=24). Block: out tile 128t x 64d over s in [sc*256, sc*256+256) ∩ [0, t0+128).
__global__ __launch_bounds__(256, 2)
void favw_mma() {
    extern __shared__ float sm2[];
    float (*Qs)[68]  = (float(*)[68])sm2;                       // [t 128][d]
    float (*Ks)[68]  = (float(*)[68])(sm2 + 128 * 68);          // [s 64][d]
    float (*Vs)[68]  = (float(*)[68])(sm2 + 192 * 68);          // [s 64][d]
    float (*Ws)[132] = (float(*)[132])(sm2 + 256 * 68);         // [s 64][t 128]
    int tT = (Tn / 128 - 1) - blockIdx.x;
    int sc = blockIdx.y, bh = blockIdx.z;
    int t0 = tT * 128;
    int sBase = sc * 256;
    if (sBase >= t0 + 128) return;
    int b = bh / Hn, h = bh % Hn;
    const float* Kb = g_k  + (size_t)bh * Tn * HSn;
    const float* Vb = g_vp + (size_t)bh * Tn * HSn;
    const float* Qp = g_q  + (size_t)bh * Tn * HSn + (size_t)t0 * HSn;
    int tid = threadIdx.x, l = tid & 31, w = tid >> 5;
    int g = l >> 2, tg = l & 3;
    #pragma unroll
    for (int i = 0; i < 8; i++) {
        int idx = tid + i * 256;
        int r = idx >> 4, dv = (idx & 15) * 4;
        float4 v = *(const float4*)&Qp[(size_t)r * HSn + dv];
        Qs[r][dv + 0] = tf32r(v.x); Qs[r][dv + 1] = tf32r(v.y);
        Qs[r][dv + 2] = tf32r(v.z); Qs[r][dv + 3] = tf32r(v.w);
    }
    int wmS = (w & 1) * 32, wnS = (w >> 1) * 32;   // S: 64s x 128t
    int wmO = (w & 3) * 32, wnO = (w >> 2) * 32;   // out: 128t x 64d
    float acco[2][4][4] = {};
    #pragma unroll 1
    for (int j = 0; j < 4; j++) {
        int s0 = sBase + j * 64;
        if (s0 >= t0 + 128) break;
        __syncthreads();
        #pragma unroll
        for (int i = 0; i < 4; i++) {
            int idx = tid + i * 256;
            int r = idx >> 4, dv = (idx & 15) * 4;
            float4 kv = *(const float4*)&Kb[(size_t)(s0 + r) * HSn + dv];
            float4 vv = *(const float4*)&Vb[(size_t)(s0 + r) * HSn + dv];
            Ks[r][dv + 0] = tf32r(kv.x); Ks[r][dv + 1] = tf32r(kv.y);
            Ks[r][dv + 2] = tf32r(kv.z); Ks[r][dv + 3] = tf32r(kv.w);
            Vs[r][dv + 0] = tf32r(vv.x); Vs[r][dv + 1] = tf32r(vv.y);
            Vs[r][dv + 2] = tf32r(vv.z); Vs[r][dv + 3] = tf32r(vv.w);
        }
        __syncthreads();
        float accs[2][4][4] = {};
        #pragma unroll
        for (int kk = 0; kk < 64; kk += 8) {
            unsigned a[2][4], bfr[4][2];
            #pragma unroll
            for (int im = 0; im < 2; im++) {
                int r = wmS + im * 16;
                a[im][0] = __float_as_uint(Ks[r + g][kk + tg]);
                a[im][1] = __float_as_uint(Ks[r + 8 + g][kk + tg]);
                a[im][2] = __float_as_uint(Ks[r + g][kk + 4 + tg]);
                a[im][3] = __float_as_uint(Ks[r + 8 + g][kk + 4 + tg]);
            }
            #pragma unroll
            for (int jn = 0; jn < 4; jn++) {
                int c = wnS + jn * 8;
                bfr[jn][0] = __float_as_uint(Qs[c + g][kk + tg]);
                bfr[jn][1] = __float_as_uint(Qs[c + g][kk + 4 + tg]);
            }
            #pragma unroll
            for (int im = 0; im < 2; im++)
                #pragma unroll
                for (int jn = 0; jn < 4; jn++) mma8(accs[im][jn], a[im], bfr[jn]);
        }
        #pragma unroll
        for (int im = 0; im < 2; im++) {
            #pragma unroll
            for (int half = 0; half < 2; half++) {
                int s_loc = wmS + im * 16 + g + half * 8;
                int s_glob = s0 + s_loc;
                #pragma unroll
                for (int jn = 0; jn < 4; jn++) {
                    #pragma unroll
                    for (int c2 = 0; c2 < 2; c2++) {
                        int t_loc = wnS + jn * 8 + tg * 2 + c2;
                        int t_glob = t0 + t_loc;
                        float e = __expf(accs[im][jn][half * 2 + c2] * SCALE);
                        if (t_glob < s_glob) e = 0.f;
                        Ws[s_loc][t_loc] = tf32r(e);
                    }
                }
            }
        }
        __syncthreads();
        #pragma unroll
        for (int kk = 0; kk < 64; kk += 8) {
            unsigned a[2][4], bf2[4][2];
            #pragma unroll
            for (int im = 0; im < 2; im++) {
                int r = wmO + im * 16;
                a[im][0] = __float_as_uint(Ws[kk + tg][r + g]);
                a[im][1] = __float_as_uint(Ws[kk + tg][r + 8 + g]);
                a[im][2] = __float_as_uint(Ws[kk + 4 + tg][r + g]);
                a[im][3] = __float_as_uint(Ws[kk + 4 + tg][r + 8 + g]);
            }
            #pragma unroll
            for (int jn = 0; jn < 4; jn++) {
                int c = wnO + jn * 8;
                bf2[jn][0] = __float_as_uint(Vs[kk + tg][c + g]);
                bf2[jn][1] = __float_as_uint(Vs[kk + 4 + tg][c + g]);
            }
            #pragma unroll
            for (int im = 0; im < 2; im++)
                #pragma unroll
                for (int jn = 0; jn < 4; jn++) mma8(acco[im][jn], a[im], bf2[jn]);
        }
    }
    // RED-accumulate partial out tile into g_attn (head-merged)
    #pragma unroll
    for (int im = 0; im < 2; im++) {
        #pragma unroll
        for (int half = 0; half < 2; half++) {
            int t = t0 + wmO + im * 16 + g + half * 8;
            float* orow = g_attn + (size_t)(b * Tn + t) * Cn + h * HSn;
            #pragma unroll
            for (int jn = 0; jn < 4; jn++) {
                int d = wnO + jn * 8 + tg * 2;
                red2(&orow[d], acco[im][jn][half * 2], acco[im][jn][half * 2 + 1]);
            }
        }
    }
}

// ------------------------- launch -------------------------
extern "C" void kernel_launch(void* const* d_in, const int* in_sizes, int n_in,
                              void* d_out, int out_size) {
    const float* x      = (const float*)d_in[0];
    const float* wq     = (const float*)d_in[1];
    const float* wk     = (const float*)d_in[2];
    const float* wv     = (const float*)d_in[3];
    const float* w_proj = (const float*)d_in[4];
    const float* b_proj = (const float*)d_in[5];
    const float* w1     = (const float*)d_in[6];
    const float* b1     = (const float*)d_in[7];
    const float* w2     = (const float*)d_in[8];
    const float* b2     = (const float*)d_in[9];
    const float* g1     = (const float*)d_in[10];
    const float* be1    = (const float*)d_in[11];
    const float* g2     = (const float*)d_in[12];
    const float* be2    = (const float*)d_in[13];
    float* out = (float*)d_out;

    float *p_h, *p_x1, *p_attn, *p_f1, *p_z;
    cudaGetSymbolAddress((void**)&p_h,    g_h);
    cudaGetSymbolAddress((void**)&p_x1,   g_x1);
    cudaGetSymbolAddress((void**)&p_attn, g_attn);
    cudaGetSymbolAddress((void**)&p_f1,   g_f1);
    cudaGetSymbolAddress((void**)&p_z,    g_z);

    int smem1 = 2 * 128 * 68 * (int)sizeof(float);           // 69632
    int smem2 = (256 * 68 + 64 * 132) * (int)sizeof(float);  // 103424
    cudaFuncSetAttribute(zsum_mma, cudaFuncAttributeMaxDynamicSharedMemorySize, smem1);
    cudaFuncSetAttribute(favw_mma, cudaFuncAttributeMaxDynamicSharedMemorySize, smem2);

    // 0. zero accumulators
    cudaMemsetAsync(p_z, 0, (size_t)BHn * Tn * sizeof(float));
    cudaMemsetAsync(p_attn, 0, (size_t)BTn * Cn * sizeof(float));
    // 1. LN1
    ln_kernel<<<BTn, 128>>>(x, g1, be1, p_h);
    // 2. QKV projections
    qkv_mma<<<dim3(BTn / 128, Hn, 3), 256>>>(wq, wk, wv);
    // 3. Pass 1: Z sums (no max; atomic accumulate)
    zsum_mma<<<dim3(Tn / 128, Tn / 128, BHn), 256, smem1>>>();
    // 4. Fold 1/Z into V
    vscale_kernel<<<(BHn * Tn * HSn / 4) / 256, 256>>>();
    // 5. Pass 2: fused recompute + weight + AV partials, RED accumulate
    favw_mma<<<dim3(Tn / 128, 8, BHn), 256, smem2>>>();
    // 6. Output projection + residual 1
    gemm_mma<1><<<dim3(Cn / 64, BTn / 128), 256>>>(p_attn, w_proj, b_proj, x, p_x1, Cn, Cn);
    // 7. LN2
    ln_kernel<<<BTn, 128>>>(p_x1, g2, be2, p_h);
    // 8. MLP up + relu
    gemm_mma<0><<<dim3(C4n / 64, BTn / 128), 256>>>(p_h, w1, b1, nullptr, p_f1, C4n, Cn);
    // 9. MLP down + residual 2 -> out
    gemm_mma<1><<<dim3(Cn / 64, BTn / 128), 256>>>(p_f1, w2, b2, p_x1, out, Cn, C4n);
}

// round 7
// speedup vs baseline: 1.8260x; 1.5592x over previous
#include <cuda_runtime.h>
#include <cuda_fp16.h>
#include <math.h>

#define Bv   4
#define Tn   2048
#define Cn   384
#define Hn   6
#define HSn  64
#define BTn  8192
#define BHn  24
#define C4n  1536

// ------------------------- scratch (static device globals) -------------------------
__device__ float  g_h[BTn * Cn];
__device__ float  g_q[BHn * Tn * HSn];
__device__ float  g_k[BHn * Tn * HSn];
__device__ float  g_v[BHn * Tn * HSn];
__device__ float  g_vp[BHn * Tn * HSn];              // V / Z[s]
__device__ float  g_z[BHn * Tn];                     // per-key sum of exp(S)
__device__ __half g_sw[(size_t)BHn * Tn * Tn];       // unnormalized weights exp(S), fp16 (201MB)
__device__ float  g_attn[BTn * Cn];
__device__ float  g_x1[BTn * Cn];
__device__ float  g_f1[BTn * C4n];

#define SCALE 0.05103103630798287f       // 384^-0.5

// ------------------------- tf32 mma helpers -------------------------
__device__ __forceinline__ float tf32r(float x) {
    unsigned u;
    asm("cvt.rna.tf32.f32 %0, %1;" : "=r"(u) : "f"(x));
    return __uint_as_float(u);
}

__device__ __forceinline__ void mma8(float* c, const unsigned* a, const unsigned* b) {
    asm volatile(
        "mma.sync.aligned.m16n8k8.row.col.f32.tf32.tf32.f32 "
        "{%0,%1,%2,%3}, {%4,%5,%6,%7}, {%8,%9}, {%0,%1,%2,%3};\n"
        : "+f"(c[0]), "+f"(c[1]), "+f"(c[2]), "+f"(c[3])
        : "r"(a[0]), "r"(a[1]), "r"(a[2]), "r"(a[3]), "r"(b[0]), "r"(b[1]));
}

__device__ __forceinline__ void red2(float* p, float x, float y) {
    asm volatile("red.global.add.v2.f32 [%0], {%1,%2};" :: "l"(p), "f"(x), "f"(y) : "memory");
}

// ------------------------- LayerNorm -------------------------
__global__ void ln_kernel(const float* __restrict__ in, const float* __restrict__ gamma,
                          const float* __restrict__ beta, float* __restrict__ out) {
    int row = blockIdx.x;
    int tid = threadIdx.x;
    const float* p = in + row * Cn;
    float v0 = p[tid], v1 = p[tid + 128], v2 = p[tid + 256];
    float s = v0 + v1 + v2;
    __shared__ float red[4];
    #pragma unroll
    for (int o = 16; o > 0; o >>= 1) s += __shfl_xor_sync(0xffffffffu, s, o);
    if ((tid & 31) == 0) red[tid >> 5] = s;
    __syncthreads();
    float mean = (red[0] + red[1] + red[2] + red[3]) * (1.0f / Cn);
    __syncthreads();
    float d0 = v0 - mean, d1 = v1 - mean, d2 = v2 - mean;
    float q = d0 * d0 + d1 * d1 + d2 * d2;
    #pragma unroll
    for (int o = 16; o > 0; o >>= 1) q += __shfl_xor_sync(0xffffffffu, q, o);
    if ((tid & 31) == 0) red[tid >> 5] = q;
    __syncthreads();
    float var = (red[0] + red[1] + red[2] + red[3]) * (1.0f / Cn);
    float r = rsqrtf(var + 1e-5f);
    float* o = out + row * Cn;
    o[tid]       = d0 * r * gamma[tid]       + beta[tid];
    o[tid + 128] = d1 * r * gamma[tid + 128] + beta[tid + 128];
    o[tid + 256] = d2 * r * gamma[tid + 256] + beta[tid + 256];
}

// ------------------------- generic GEMM (tf32 mma) -------------------------
template <int EPI>
__global__ __launch_bounds__(256)
void gemm_mma(const float* __restrict__ A, const float* __restrict__ Bw,
              const float* __restrict__ bias, const float* __restrict__ resid,
              float* __restrict__ Co, int N, int K) {
    __shared__ float As[128][36];
    __shared__ float Bs[32][68];
    int m0 = blockIdx.y * 128, n0 = blockIdx.x * 64;
    int tid = threadIdx.x, l = tid & 31, w = tid >> 5;
    int wm = (w & 3) * 32, wn = (w >> 2) * 32;
    int g = l >> 2, tg = l & 3;
    float acc[2][4][4] = {};
    for (int k0 = 0; k0 < K; k0 += 32) {
        #pragma unroll
        for (int i = 0; i < 4; i++) {
            int idx = tid + i * 256;
            int m = idx >> 3, kv = (idx & 7) * 4;
            float4 v = *(const float4*)&A[(size_t)(m0 + m) * K + k0 + kv];
            As[m][kv + 0] = tf32r(v.x); As[m][kv + 1] = tf32r(v.y);
            As[m][kv + 2] = tf32r(v.z); As[m][kv + 3] = tf32r(v.w);
        }
        #pragma unroll
        for (int i = 0; i < 2; i++) {
            int idx = tid + i * 256;
            int k = idx >> 4, nv = (idx & 15) * 4;
            float4 v = *(const float4*)&Bw[(size_t)(k0 + k) * N + n0 + nv];
            Bs[k][nv + 0] = tf32r(v.x); Bs[k][nv + 1] = tf32r(v.y);
            Bs[k][nv + 2] = tf32r(v.z); Bs[k][nv + 3] = tf32r(v.w);
        }
        __syncthreads();
        #pragma unroll
        for (int kk = 0; kk < 32; kk += 8) {
            unsigned a[2][4], b[4][2];
            #pragma unroll
            for (int im = 0; im < 2; im++) {
                int r = wm + im * 16;
                a[im][0] = __float_as_uint(As[r + g][kk + tg]);
                a[im][1] = __float_as_uint(As[r + 8 + g][kk + tg]);
                a[im][2] = __float_as_uint(As[r + g][kk + 4 + tg]);
                a[im][3] = __float_as_uint(As[r + 8 + g][kk + 4 + tg]);
            }
            #pragma unroll
            for (int jn = 0; jn < 4; jn++) {
                int c = wn + jn * 8;
                b[jn][0] = __float_as_uint(Bs[kk + tg][c + g]);
                b[jn][1] = __float_as_uint(Bs[kk + 4 + tg][c + g]);
            }
            #pragma unroll
            for (int im = 0; im < 2; im++)
                #pragma unroll
                for (int jn = 0; jn < 4; jn++) mma8(acc[im][jn], a[im], b[jn]);
        }
        __syncthreads();
    }
    #pragma unroll
    for (int im = 0; im < 2; im++) {
        int r0 = m0 + wm + im * 16 + g;
        #pragma unroll
        for (int jn = 0; jn < 4; jn++) {
            int c = n0 + wn + jn * 8 + tg * 2;
            float b0v = bias[c], b1v = bias[c + 1];
            float v00 = acc[im][jn][0] + b0v, v01 = acc[im][jn][1] + b1v;
            float v10 = acc[im][jn][2] + b0v, v11 = acc[im][jn][3] + b1v;
            if (EPI == 0) {
                v00 = fmaxf(v00, 0.f); v01 = fmaxf(v01, 0.f);
                v10 = fmaxf(v10, 0.f); v11 = fmaxf(v11, 0.f);
            } else {
                v00 += resid[(size_t)r0 * N + c];       v01 += resid[(size_t)r0 * N + c + 1];
                v10 += resid[(size_t)(r0 + 8) * N + c]; v11 += resid[(size_t)(r0 + 8) * N + c + 1];
            }
            Co[(size_t)r0 * N + c] = v00;       Co[(size_t)r0 * N + c + 1] = v01;
            Co[(size_t)(r0 + 8) * N + c] = v10; Co[(size_t)(r0 + 8) * N + c + 1] = v11;
        }
    }
}

// ------------------------- QKV (tf32 mma) -------------------------
__global__ __launch_bounds__(256)
void qkv_mma(const float* __restrict__ wq, const float* __restrict__ wk,
             const float* __restrict__ wv) {
    __shared__ float As[128][36];
    __shared__ float Bs[32][68];
    int hh = blockIdx.y;
    const float* W;
    float* O;
    if (blockIdx.z == 0)      { W = wq; O = g_q; }
    else if (blockIdx.z == 1) { W = wk; O = g_k; }
    else                      { W = wv; O = g_v; }
    W += hh * Cn * HSn;
    int m0 = blockIdx.x * 128;
    int tid = threadIdx.x, l = tid & 31, w = tid >> 5;
    int wm = (w & 3) * 32, wn = (w >> 2) * 32;
    int g = l >> 2, tg = l & 3;
    float acc[2][4][4] = {};
    for (int k0 = 0; k0 < Cn; k0 += 32) {
        #pragma unroll
        for (int i = 0; i < 4; i++) {
            int idx = tid + i * 256;
            int m = idx >> 3, kv = (idx & 7) * 4;
            float4 v = *(const float4*)&g_h[(size_t)(m0 + m) * Cn + k0 + kv];
            As[m][kv + 0] = tf32r(v.x); As[m][kv + 1] = tf32r(v.y);
            As[m][kv + 2] = tf32r(v.z); As[m][kv + 3] = tf32r(v.w);
        }
        {
            int idx = tid;
            #pragma unroll
            for (int i = 0; i < 2; i++) {
                int k = idx >> 4, nv = (idx & 15) * 4;
                float4 v = *(const float4*)&W[(size_t)(k0 + k) * HSn + nv];
                Bs[k][nv + 0] = tf32r(v.x); Bs[k][nv + 1] = tf32r(v.y);
                Bs[k][nv + 2] = tf32r(v.z); Bs[k][nv + 3] = tf32r(v.w);
                idx += 256;
            }
        }
        __syncthreads();
        #pragma unroll
        for (int kk = 0; kk < 32; kk += 8) {
            unsigned a[2][4], b[4][2];
            #pragma unroll
            for (int im = 0; im < 2; im++) {
                int r = wm + im * 16;
                a[im][0] = __float_as_uint(As[r + g][kk + tg]);
                a[im][1] = __float_as_uint(As[r + 8 + g][kk + tg]);
                a[im][2] = __float_as_uint(As[r + g][kk + 4 + tg]);
                a[im][3] = __float_as_uint(As[r + 8 + g][kk + 4 + tg]);
            }
            #pragma unroll
            for (int jn = 0; jn < 4; jn++) {
                int c = wn + jn * 8;
                b[jn][0] = __float_as_uint(Bs[kk + tg][c + g]);
                b[jn][1] = __float_as_uint(Bs[kk + 4 + tg][c + g]);
            }
            #pragma unroll
            for (int im = 0; im < 2; im++)
                #pragma unroll
                for (int jn = 0; jn < 4; jn++) mma8(acc[im][jn], a[im], b[jn]);
        }
        __syncthreads();
    }
    #pragma unroll
    for (int im = 0; im < 2; im++) {
        #pragma unroll
        for (int half = 0; half < 2; half++) {
            int m = m0 + wm + im * 16 + g + half * 8;
            int b = m >> 11, t = m & (Tn - 1);
            float* orow = O + (((size_t)(b * Hn + hh) * Tn + t) * HSn);
            #pragma unroll
            for (int jn = 0; jn < 4; jn++) {
                int c = wn + jn * 8 + tg * 2;
                orow[c]     = acc[im][jn][half * 2];
                orow[c + 1] = acc[im][jn][half * 2 + 1];
            }
        }
    }
}

// ------------------------- wsum: W = exp(scale*K·Qt) stored fp16, Z row-sums via atomics -------------------------
// grid (tT=16, sT=16, bh=24); tiles with tT < sT skipped. One pass, no softmax kernel needed.
__global__ __launch_bounds__(256)
void wsum_mma() {
    extern __shared__ float sm1[];
    float (*Ks)[68] = (float(*)[68])sm1;               // [s][d]
    float (*Qs)[68] = (float(*)[68])(sm1 + 128 * 68);  // [t][d]
    int tT = blockIdx.x, sT = blockIdx.y, bh = blockIdx.z;
    if (tT < sT) return;
    const float* Kp = g_k + (size_t)bh * Tn * HSn + (size_t)sT * 128 * HSn;
    const float* Qp = g_q + (size_t)bh * Tn * HSn + (size_t)tT * 128 * HSn;
    __half* Wh = g_sw + (size_t)bh * Tn * Tn;
    int tid = threadIdx.x, l = tid & 31, w = tid >> 5;
    int g = l >> 2, tg = l & 3;
    int wm = (w & 3) * 32, wn = (w >> 2) * 64;
    #pragma unroll
    for (int i = 0; i < 8; i++) {
        int idx = tid + i * 256;
        int r = idx >> 4, dv = (idx & 15) * 4;
        float4 a = *(const float4*)&Kp[(size_t)r * HSn + dv];
        float4 b = *(const float4*)&Qp[(size_t)r * HSn + dv];
        Ks[r][dv + 0] = tf32r(a.x); Ks[r][dv + 1] = tf32r(a.y);
        Ks[r][dv + 2] = tf32r(a.z); Ks[r][dv + 3] = tf32r(a.w);
        Qs[r][dv + 0] = tf32r(b.x); Qs[r][dv + 1] = tf32r(b.y);
        Qs[r][dv + 2] = tf32r(b.z); Qs[r][dv + 3] = tf32r(b.w);
    }
    __syncthreads();
    float acc[2][8][4] = {};
    #pragma unroll
    for (int kk = 0; kk < 64; kk += 8) {
        unsigned a[2][4], b[8][2];
        #pragma unroll
        for (int im = 0; im < 2; im++) {
            int r = wm + im * 16;
            a[im][0] = __float_as_uint(Ks[r + g][kk + tg]);
            a[im][1] = __float_as_uint(Ks[r + 8 + g][kk + tg]);
            a[im][2] = __float_as_uint(Ks[r + g][kk + 4 + tg]);
            a[im][3] = __float_as_uint(Ks[r + 8 + g][kk + 4 + tg]);
        }
        #pragma unroll
        for (int jn = 0; jn < 8; jn++) {
            int c = wn + jn * 8;
            b[jn][0] = __float_as_uint(Qs[c + g][kk + tg]);
            b[jn][1] = __float_as_uint(Qs[c + g][kk + 4 + tg]);
        }
        #pragma unroll
        for (int im = 0; im < 2; im++)
            #pragma unroll
            for (int jn = 0; jn < 8; jn++) mma8(acc[im][jn], a[im], b[jn]);
    }
    bool diag = (tT == sT);
    #pragma unroll
    for (int im = 0; im < 2; im++) {
        #pragma unroll
        for (int half = 0; half < 2; half++) {
            int s_loc = wm + im * 16 + g + half * 8;
            int s_glob = sT * 128 + s_loc;
            float ls = 0.f;
            #pragma unroll
            for (int jn = 0; jn < 8; jn++) {
                int t_loc = wn + jn * 8 + tg * 2;
                int t_glob = tT * 128 + t_loc;
                float e0 = __expf(acc[im][jn][half * 2]     * SCALE);
                float e1 = __expf(acc[im][jn][half * 2 + 1] * SCALE);
                if (diag) {
                    if (t_glob < s_glob)     e0 = 0.f;
                    if (t_glob + 1 < s_glob) e1 = 0.f;
                }
                __half2 h2 = __floats2half2_rn(e0, e1);
                *(__half2*)&Wh[(size_t)s_glob * Tn + t_glob] = h2;
                ls += __half2float(h2.x) + __half2float(h2.y);
            }
            ls += __shfl_xor_sync(0xffffffffu, ls, 1);
            ls += __shfl_xor_sync(0xffffffffu, ls, 2);
            if (tg == 0) atomicAdd(&g_z[bh * Tn + s_glob], ls);
        }
    }
}

// ------------------------- V' = V / Z[s] -------------------------
__global__ void vscale_kernel() {
    int idx = blockIdx.x * 256 + threadIdx.x;            // float4 index
    int row = idx >> 4;                                  // HSn/4 = 16 float4 per row
    float inv = __fdividef(1.0f, g_z[row]);
    float4 v = ((const float4*)g_v)[idx];
    v.x *= inv; v.y *= inv; v.z *= inv; v.w *= inv;
    ((float4*)g_vp)[idx] = v;
}

// ------------------------- AV: out[t,d] = sum_s W[s,t]*V'[s,d], split-s, RED accumulate -------------------------
// grid (tT=16, sc=8, bh=24). Block: out tile 128t x 64d over s in [sc*256, sc*256+256) ∩ [0, t0+128).
__global__ __launch_bounds__(256, 2)
void av_mma2() {
    extern __shared__ float sm2[];
    float (*Ws)[132] = (float(*)[132])sm2;              // [s 64][t 128]
    float (*Vs)[68]  = (float(*)[68])(sm2 + 64 * 132);  // [s 64][d]
    int tT = blockIdx.x, sc = blockIdx.y, bh = blockIdx.z;
    int t0 = tT * 128;
    int sBase = sc * 256;
    if (sBase >= t0 + 128) return;
    int b = bh / Hn, h = bh % Hn;
    const __half* Wh = g_sw + (size_t)bh * Tn * Tn;
    const float*  Vb = g_vp + (size_t)bh * Tn * HSn;
    int tid = threadIdx.x, l = tid & 31, w = tid >> 5;
    int g = l >> 2, tg = l & 3;
    int wmO = (w & 3) * 32, wnO = (w >> 2) * 32;        // out: 128t(4 warps) x 64d(2 warps)
    float acco[2][4][4] = {};
    #pragma unroll 1
    for (int j = 0; j < 4; j++) {
        int s0 = sBase + j * 64;
        if (s0 >= t0 + 128) break;
        __syncthreads();
        #pragma unroll
        for (int i = 0; i < 4; i++) {
            int idx = tid + i * 256;
            int r = idx >> 4, dv = (idx & 15) * 4;
            float4 vv = *(const float4*)&Vb[(size_t)(s0 + r) * HSn + dv];
            Vs[r][dv + 0] = tf32r(vv.x); Vs[r][dv + 1] = tf32r(vv.y);
            Vs[r][dv + 2] = tf32r(vv.z); Vs[r][dv + 3] = tf32r(vv.w);
        }
        #pragma unroll
        for (int i = 0; i < 4; i++) {
            int lin = tid + i * 256;
            int r = lin >> 4, c8 = (lin & 15) * 8;
            int4 pk = *(const int4*)&Wh[(size_t)(s0 + r) * Tn + t0 + c8];
            __half2 h0 = *(__half2*)&pk.x, h1 = *(__half2*)&pk.y;
            __half2 h2 = *(__half2*)&pk.z, h3 = *(__half2*)&pk.w;
            Ws[r][c8 + 0] = __half2float(h0.x); Ws[r][c8 + 1] = __half2float(h0.y);
            Ws[r][c8 + 2] = __half2float(h1.x); Ws[r][c8 + 3] = __half2float(h1.y);
            Ws[r][c8 + 4] = __half2float(h2.x); Ws[r][c8 + 5] = __half2float(h2.y);
            Ws[r][c8 + 6] = __half2float(h3.x); Ws[r][c8 + 7] = __half2float(h3.y);
        }
        __syncthreads();
        // out[t][d] += W^T (A from Ws[s][t]) @ V' (B, [k=s][n=d])
        #pragma unroll
        for (int kk = 0; kk < 64; kk += 8) {
            unsigned a[2][4], bf2[4][2];
            #pragma unroll
            for (int im = 0; im < 2; im++) {
                int r = wmO + im * 16;
                a[im][0] = __float_as_uint(Ws[kk + tg][r + g]);
                a[im][1] = __float_as_uint(Ws[kk + tg][r + 8 + g]);
                a[im][2] = __float_as_uint(Ws[kk + 4 + tg][r + g]);
                a[im][3] = __float_as_uint(Ws[kk + 4 + tg][r + 8 + g]);
            }
            #pragma unroll
            for (int jn = 0; jn < 4; jn++) {
                int c = wnO + jn * 8;
                bf2[jn][0] = __float_as_uint(Vs[kk + tg][c + g]);
                bf2[jn][1] = __float_as_uint(Vs[kk + 4 + tg][c + g]);
            }
            #pragma unroll
            for (int im = 0; im < 2; im++)
                #pragma unroll
                for (int jn = 0; jn < 4; jn++) mma8(acco[im][jn], a[im], bf2[jn]);
        }
    }
    // RED-accumulate partial out tile into g_attn (head-merged)
    #pragma unroll
    for (int im = 0; im < 2; im++) {
        #pragma unroll
        for (int half = 0; half < 2; half++) {
            int t = t0 + wmO + im * 16 + g + half * 8;
            float* orow = g_attn + (size_t)(b * Tn + t) * Cn + h * HSn;
            #pragma unroll
            for (int jn = 0; jn < 4; jn++) {
                int d = wnO + jn * 8 + tg * 2;
                red2(&orow[d], acco[im][jn][half * 2], acco[im][jn][half * 2 + 1]);
            }
        }
    }
}

// ------------------------- launch -------------------------
extern "C" void kernel_launch(void* const* d_in, const int* in_sizes, int n_in,
                              void* d_out, int out_size) {
    const float* x      = (const float*)d_in[0];
    const float* wq     = (const float*)d_in[1];
    const float* wk     = (const float*)d_in[2];
    const float* wv     = (const float*)d_in[3];
    const float* w_proj = (const float*)d_in[4];
    const float* b_proj = (const float*)d_in[5];
    const float* w1     = (const float*)d_in[6];
    const float* b1     = (const float*)d_in[7];
    const float* w2     = (const float*)d_in[8];
    const float* b2     = (const float*)d_in[9];
    const float* g1     = (const float*)d_in[10];
    const float* be1    = (const float*)d_in[11];
    const float* g2     = (const float*)d_in[12];
    const float* be2    = (const float*)d_in[13];
    float* out = (float*)d_out;

    float *p_h, *p_x1, *p_attn, *p_f1, *p_z;
    cudaGetSymbolAddress((void**)&p_h,    g_h);
    cudaGetSymbolAddress((void**)&p_x1,   g_x1);
    cudaGetSymbolAddress((void**)&p_attn, g_attn);
    cudaGetSymbolAddress((void**)&p_f1,   g_f1);
    cudaGetSymbolAddress((void**)&p_z,    g_z);

    int smem1 = 2 * 128 * 68 * (int)sizeof(float);            // 69632
    int smem2 = (64 * 132 + 64 * 68) * (int)sizeof(float);    // 51200
    cudaFuncSetAttribute(wsum_mma, cudaFuncAttributeMaxDynamicSharedMemorySize, smem1);
    cudaFuncSetAttribute(av_mma2,  cudaFuncAttributeMaxDynamicSharedMemorySize, smem2);

    // 0. zero accumulators
    cudaMemsetAsync(p_z, 0, (size_t)BHn * Tn * sizeof(float));
    cudaMemsetAsync(p_attn, 0, (size_t)BTn * Cn * sizeof(float));
    // 1. LN1
    ln_kernel<<<BTn, 128>>>(x, g1, be1, p_h);
    // 2. QKV projections
    qkv_mma<<<dim3(BTn / 128, Hn, 3), 256>>>(wq, wk, wv);
    // 3. Weights (fp16) + Z row sums, one pass
    wsum_mma<<<dim3(Tn / 128, Tn / 128, BHn), 256, smem1>>>();
    // 4. Fold 1/Z into V
    vscale_kernel<<<(BHn * Tn * HSn / 4) / 256, 256>>>();
    // 5. AV (fp16 weights), split-s, RED accumulate
    av_mma2<<<dim3(Tn / 128, 8, BHn), 256, smem2>>>();
    // 6. Output projection + residual 1
    gemm_mma<1><<<dim3(Cn / 64, BTn / 128), 256>>>(p_attn, w_proj, b_proj, x, p_x1, Cn, Cn);
    // 7. LN2
    ln_kernel<<<BTn, 128>>>(p_x1, g2, be2, p_h);
    // 8. MLP up + relu
    gemm_mma<0><<<dim3(C4n / 64, BTn / 128), 256>>>(p_h, w1, b1, nullptr, p_f1, C4n, Cn);
    // 9. MLP down + residual 2 -> out
    gemm_mma<1><<<dim3(Cn / 64, BTn / 128), 256>>>(p_f1, w2, b2, p_x1, out, Cn, C4n);
}